// round 4
// baseline (speedup 1.0000x reference)
#include <cuda_runtime.h>

#define BB   16
#define NN   1024
#define INF  256
#define HH   4
#define DD   64
#define CC   256      // HH*DD
#define NEG_SLOPE 0.2f
#define WS_HSTR 2056  // floats per head region in wsd: 32*32*2 + 8 pad (8-bank offset)

// ---- scratch (device globals: no allocation allowed) ----
__device__ float g_h[BB * NN * CC];                  // 16 MB: h = x @ W
__device__ float g_ssrc[BB * NN * HH];
__device__ float g_sdst[BB * NN * HH];
__device__ float g_mx[BB * HH];                      // max_j s_dst per (b,h)
__device__ unsigned g_mask[BB * NN * (NN / 32)];     // 2 MB adjacency bitmask

// ---- f32x2 packed helpers (sm_103a FFMA2) ----
__device__ __forceinline__ unsigned long long pack2(float w) {
    unsigned long long r;
    asm("mov.b64 %0, {%1, %1};" : "=l"(r) : "f"(w));
    return r;
}
__device__ __forceinline__ unsigned long long packpair(float a, float b) {
    unsigned long long r;
    asm("mov.b64 %0, {%1, %2};" : "=l"(r) : "f"(a), "f"(b));
    return r;
}
__device__ __forceinline__ void fma2(unsigned long long& acc, unsigned long long a, unsigned long long b) {
    asm("fma.rn.f32x2 %0, %1, %2, %0;" : "+l"(acc) : "l"(a), "l"(b));
}
__device__ __forceinline__ void fadd2(unsigned long long& acc, unsigned long long a) {
    asm("add.rn.f32x2 %0, %0, %1;" : "+l"(acc) : "l"(a));
}
__device__ __forceinline__ float2 unpack2(unsigned long long v) {
    float2 f;
    asm("mov.b64 {%0, %1}, %2;" : "=f"(f.x), "=f"(f.y) : "l"(v));
    return f;
}

// ============================================================
// 0) adjacency -> bitmask (one warp produces one 32-bit word)
// ============================================================
__global__ __launch_bounds__(256) void mask_kernel(const int* __restrict__ adj)
{
    int gid = blockIdx.x * 256 + threadIdx.x;
    unsigned word = __ballot_sync(0xffffffffu, adj[gid] > 0);
    if ((threadIdx.x & 31) == 0) g_mask[gid >> 5] = word;
}

// ============================================================
// 1) h = x @ W : [16384,256]@[256,256]. 64x128 tiles, 4x8 micro, f32x2.
//    A stored duplicated in smem -> LDS.64 yields packed (a,a).
// ============================================================
__global__ __launch_bounds__(256) void gemm_kernel(const float* __restrict__ A,
                                                   const float* __restrict__ Bm)
{
    __shared__ __align__(16) float Astd[32 * 130];   // [k][2*m(+pad)] duplicated pairs
    __shared__ __align__(16) float Bs[32 * 128];     // [k][n]

    int t  = threadIdx.x;
    int ty = t >> 4, tx = t & 15;                    // ty: 4-row group, tx: 8-col group
    int rowBase = blockIdx.y << 6;
    int colBase = blockIdx.x << 7;

    unsigned long long acc[4][4];
    #pragma unroll
    for (int r = 0; r < 4; ++r)
        #pragma unroll
        for (int q = 0; q < 4; ++q) acc[r][q] = 0ull;

    for (int k0 = 0; k0 < 256; k0 += 32) {
        // A tile 64x32, transposed + duplicated
        #pragma unroll
        for (int l = 0; l < 8; ++l) {
            int idx = t + (l << 8);
            int ar = idx >> 5, ak = idx & 31;
            float v = A[(rowBase + ar) * 256 + k0 + ak];
            *(float2*)&Astd[ak * 130 + (ar << 1)] = make_float2(v, v);
        }
        // B tile 32x128
        #pragma unroll
        for (int l = 0; l < 4; ++l) {
            int idx = t + (l << 8);
            int bk = idx >> 5, bc4 = idx & 31;
            *(float4*)&Bs[bk * 128 + (bc4 << 2)] =
                *(const float4*)&Bm[(k0 + bk) * 256 + colBase + (bc4 << 2)];
        }
        __syncthreads();
        #pragma unroll 8
        for (int kk = 0; kk < 32; ++kk) {
            ulonglong2 B0 = *(const ulonglong2*)&Bs[kk * 128 + (tx << 3)];
            ulonglong2 B1 = *(const ulonglong2*)&Bs[kk * 128 + (tx << 3) + 4];
            #pragma unroll
            for (int r = 0; r < 4; ++r) {
                unsigned long long a2 =
                    *(const unsigned long long*)&Astd[kk * 130 + (((ty << 2) + r) << 1)];
                fma2(acc[r][0], a2, B0.x);
                fma2(acc[r][1], a2, B0.y);
                fma2(acc[r][2], a2, B1.x);
                fma2(acc[r][3], a2, B1.y);
            }
        }
        __syncthreads();
    }
    #pragma unroll
    for (int r = 0; r < 4; ++r) {
        float2 c0 = unpack2(acc[r][0]);
        float2 c1 = unpack2(acc[r][1]);
        float2 c2 = unpack2(acc[r][2]);
        float2 c3 = unpack2(acc[r][3]);
        float* op = &g_h[(rowBase + (ty << 2) + r) * 256 + colBase + (tx << 3)];
        *(float4*)op       = make_float4(c0.x, c0.y, c1.x, c1.y);
        *(float4*)(op + 4) = make_float4(c2.x, c2.y, c3.x, c3.y);
    }
}

// ============================================================
// 2) s_src[b,n,h] = h[b,n,h,:] . a_src[:,h];  s_dst likewise
// ============================================================
__global__ __launch_bounds__(256) void score_kernel(const float* __restrict__ a)
{
    int bn = blockIdx.x;
    int c  = threadIdx.x;
    float hv = g_h[bn * 256 + c];
    int hd = c >> 6, d = c & 63;
    float ps = hv * a[d * 4 + hd];
    float pd = hv * a[(64 + d) * 4 + hd];
    #pragma unroll
    for (int o = 16; o; o >>= 1) {
        ps += __shfl_xor_sync(0xffffffffu, ps, o);
        pd += __shfl_xor_sync(0xffffffffu, pd, o);
    }
    __shared__ float rs[8], rd[8];
    if ((c & 31) == 0) { rs[c >> 5] = ps; rd[c >> 5] = pd; }
    __syncthreads();
    if (c < 4) {
        g_ssrc[bn * 4 + c] = rs[2 * c] + rs[2 * c + 1];
        g_sdst[bn * 4 + c] = rd[2 * c] + rd[2 * c + 1];
    }
}

// ============================================================
// 3) g_mx[b,h] = max_n s_dst[b,n,h]   (valid softmax shift)
// ============================================================
__global__ __launch_bounds__(256) void max_kernel()
{
    int bh = blockIdx.x;
    int b = bh >> 2, h = bh & 3;
    int t = threadIdx.x;
    float m = -3.4e38f;
    for (int n = t; n < NN; n += 256)
        m = fmaxf(m, g_sdst[((b << 10) + n) * 4 + h]);
    #pragma unroll
    for (int o = 16; o; o >>= 1) m = fmaxf(m, __shfl_xor_sync(0xffffffffu, m, o));
    __shared__ float sm_[8];
    if ((t & 31) == 0) sm_[t >> 5] = m;
    __syncthreads();
    if (t == 0) {
        float mm = sm_[0];
        #pragma unroll
        for (int i = 1; i < 8; ++i) mm = fmaxf(mm, sm_[i]);
        g_mx[bh] = mm;
    }
}

// ============================================================
// 4) attention aggregation v3:
//    128 threads (4 warps x 8 rows), thread tile 8x8, packed f32x2.
//    wsd: duplicated (w,w) pairs -> LDS.128 = 2 packed operands, no pack movs.
//    adj via 2MB bitmask (broadcast LDG). Denominator in weight phase.
//    dyn smem: wsd 4*2056 floats (32896B) + hs 32*256 (32768B) = 65664B
// ============================================================
__global__ __launch_bounds__(128, 3) void attn_kernel(float* __restrict__ out)
{
    extern __shared__ __align__(16) float dynsm[];
    float* wsd = dynsm;                    // [h][i][j*2] dup pairs, head stride 2056
    float* hs  = dynsm + 4 * WS_HSTR;      // [jj][c]

    __shared__ float4 ssrc_s[32], Ms_s[32];

    int b  = blockIdx.x >> 5;
    int i0 = (blockIdx.x & 31) << 5;
    int t  = threadIdx.x;
    int lane = t & 31, wid = t >> 5;
    int hcol = lane >> 3;                  // head of this thread's 8 output cols

    {   // 128 threads cover 32 rows x 4 heads
        int i = t >> 2, h = t & 3;
        float ss = g_ssrc[((b << 10) + i0 + i) * 4 + h];
        ((float*)&ssrc_s[i])[h] = ss;
        float m = ss + g_mx[(b << 2) + h];
        ((float*)&Ms_s[i])[h] = (m > 0.f) ? m : NEG_SLOPE * m;  // >= all logits (row i, head h)
    }

    unsigned long long acc[8][4];
    #pragma unroll
    for (int r = 0; r < 8; ++r)
        #pragma unroll
        for (int k = 0; k < 4; ++k) acc[r][k] = 0ull;
    unsigned long long dlocA[8], dlocB[8];           // per-lane partial dens (h0,h1)/(h2,h3)
    #pragma unroll
    for (int r = 0; r < 8; ++r) { dlocA[r] = 0ull; dlocB[r] = 0ull; }

    const float4* h4  = (const float4*)g_h;
    const float4* sd4 = (const float4*)g_sdst;
    const ulonglong2* hpo = (const ulonglong2*)hs + (lane << 1);
    const int mrow_base = (((b << 10) + i0 + (wid << 3)) << 5);   // mask word base

    for (int jt = 0; jt < 32; ++jt) {
        int j0 = jt << 5;
        __syncthreads();   // previous FMA phase done before overwriting smem

        // -- load h tile: 32 rows x 256 cols = 2048 float4, 16 per thread
        {
            int gbase = ((b << 10) + j0) << 6;
            #pragma unroll
            for (int l = 0; l < 16; ++l) {
                int idx = t + (l << 7);
                ((float4*)hs)[idx] = h4[gbase + idx];
            }
        }

        // -- weight tile: lane = j; 8 rows x 4 heads; store duplicated pairs
        float4 sd = sd4[(b << 10) + j0 + lane];
        #pragma unroll
        for (int r = 0; r < 8; ++r) {
            int i = (wid << 3) + r;
            unsigned mword = g_mask[mrow_base + (r << 5) + jt];
            float msk = ((mword >> lane) & 1u) ? 1.0f : 0.0f;
            float4 ss = ssrc_s[i];
            float4 Mm = Ms_s[i];
            float e0 = ss.x + sd.x; e0 = (e0 > 0.f) ? e0 : NEG_SLOPE * e0;
            float e1 = ss.y + sd.y; e1 = (e1 > 0.f) ? e1 : NEG_SLOPE * e1;
            float e2 = ss.z + sd.z; e2 = (e2 > 0.f) ? e2 : NEG_SLOPE * e2;
            float e3 = ss.w + sd.w; e3 = (e3 > 0.f) ? e3 : NEG_SLOPE * e3;
            float w0 = msk * __expf(e0 - Mm.x);
            float w1 = msk * __expf(e1 - Mm.y);
            float w2 = msk * __expf(e2 - Mm.z);
            float w3 = msk * __expf(e3 - Mm.w);
            int sb = (i << 6) + (lane << 1);
            *(float2*)(wsd + sb)               = make_float2(w0, w0);
            *(float2*)(wsd + WS_HSTR + sb)     = make_float2(w1, w1);
            *(float2*)(wsd + 2 * WS_HSTR + sb) = make_float2(w2, w2);
            *(float2*)(wsd + 3 * WS_HSTR + sb) = make_float2(w3, w3);
            fadd2(dlocA[r], packpair(w0, w1));
            fadd2(dlocB[r], packpair(w2, w3));
        }
        __syncthreads();

        // -- FMA phase: 8 rows x 8 cols per thread; 2 j per iter, zero packs
        const float* wrow = wsd + hcol * WS_HSTR + (wid << 9);
        #pragma unroll 4
        for (int jp = 0; jp < 16; ++jp) {
            ulonglong2 a0 = hpo[(jp << 7)];          // jj = 2jp
            ulonglong2 a1 = hpo[(jp << 7) + 1];
            ulonglong2 b0 = hpo[(jp << 7) + 64];     // jj = 2jp+1
            ulonglong2 b1 = hpo[(jp << 7) + 65];
            #pragma unroll
            for (int r = 0; r < 8; ++r) {
                ulonglong2 wp = *(const ulonglong2*)(wrow + (r << 6) + (jp << 2));
                fma2(acc[r][0], wp.x, a0.x);
                fma2(acc[r][1], wp.x, a0.y);
                fma2(acc[r][2], wp.x, a1.x);
                fma2(acc[r][3], wp.x, a1.y);
                fma2(acc[r][0], wp.y, b0.x);
                fma2(acc[r][1], wp.y, b0.y);
                fma2(acc[r][2], wp.y, b1.x);
                fma2(acc[r][3], wp.y, b1.y);
            }
        }
    }

    // -- cross-lane reduce of per-lane partial denominators, then store
    #pragma unroll
    for (int r = 0; r < 8; ++r) {
        #pragma unroll
        for (int off = 16; off; off >>= 1) {
            unsigned long long ta = __shfl_xor_sync(0xffffffffu, dlocA[r], off);
            unsigned long long tb = __shfl_xor_sync(0xffffffffu, dlocB[r], off);
            fadd2(dlocA[r], ta);
            fadd2(dlocB[r], tb);
        }
        float2 dA = unpack2(dlocA[r]);
        float2 dB = unpack2(dlocB[r]);
        float den = (hcol == 0) ? dA.x : (hcol == 1) ? dA.y : (hcol == 2) ? dB.x : dB.y;
        float dinv = 1.f / den;

        int i = (wid << 3) + r;
        float2 f0 = unpack2(acc[r][0]);
        float2 f1 = unpack2(acc[r][1]);
        float2 f2 = unpack2(acc[r][2]);
        float2 f3 = unpack2(acc[r][3]);
        float4* op = (float4*)out + ((((b << 10) + i0 + i) << 6) + (lane << 1));
        op[0] = make_float4(f0.x * dinv, f0.y * dinv, f1.x * dinv, f1.y * dinv);
        op[1] = make_float4(f2.x * dinv, f2.y * dinv, f3.x * dinv, f3.y * dinv);
    }
}

// ============================================================
extern "C" void kernel_launch(void* const* d_in, const int* in_sizes, int n_in,
                              void* d_out, int out_size)
{
    cudaFuncSetAttribute(attn_kernel, cudaFuncAttributeMaxDynamicSharedMemorySize, 66560);

    const float* x = nullptr; const int* adj = nullptr;
    const float* W = nullptr; const float* a = nullptr;
    for (int i = 0; i < n_in; ++i) {
        int s = in_sizes[i];
        if      (s == BB * NN * INF) x   = (const float*)d_in[i];
        else if (s == BB * NN * NN)  adj = (const int*)d_in[i];
        else if (s == INF * HH * DD) W   = (const float*)d_in[i];
        else if (s == 2 * DD * HH)   a   = (const float*)d_in[i];
    }

    mask_kernel<<<BB * NN * NN / 256, 256>>>(adj);
    gemm_kernel<<<dim3(2, 256), 256>>>(x, W);
    score_kernel<<<BB * NN, 256>>>(a);
    max_kernel<<<BB * HH, 256>>>();
    attn_kernel<<<BB * (NN / 32), 128, 65664>>>((float*)d_out);
}

// round 6
// speedup vs baseline: 2.1036x; 2.1036x over previous
#include <cuda_runtime.h>
#include <cuda_fp16.h>
#include <cstdint>

#define BB   16
#define NN   1024
#define INF  256
#define HH   4
#define DD   64
#define NEG_SLOPE 0.2f

#define SROW   144            // bytes per S row: 64 j * 2B + 16 pad (conflict-free)
#define SSIZE  (128 * 144)    // 18432 B per head
#define HROW   528            // bytes per H row: 256 c * 2B + 16 pad
#define H_OFF  (4 * SSIZE)    // 73728
#define DYN_BYTES (H_OFF + 64 * HROW)   // 107520

// ---- scratch (device globals: no allocation allowed) ----
__device__ float  g_h [BB * NN * 256];     // fp32 h (for scores)
__device__ __half g_hh[BB * NN * 256];     // fp16 h (for MMA)
__device__ float  g_ssrc[BB * NN * HH];
__device__ float  g_sdst[BB * NN * HH];
__device__ float  g_mx[BB * HH];
__device__ unsigned g_mask[BB * NN * (NN / 32)];   // 2 MB adjacency bitmask

// ---- f32x2 helpers (gemm) ----
__device__ __forceinline__ void fma2(unsigned long long& acc, unsigned long long a, unsigned long long b) {
    asm("fma.rn.f32x2 %0, %1, %2, %0;" : "+l"(acc) : "l"(a), "l"(b));
}
__device__ __forceinline__ float2 unpack2(unsigned long long v) {
    float2 f;
    asm("mov.b64 {%0, %1}, %2;" : "=f"(f.x), "=f"(f.y) : "l"(v));
    return f;
}

// ---- HMMA helpers ----
__device__ __forceinline__ uint32_t smem_u32(const void* p) {
    uint32_t a;
    asm("{ .reg .u64 t; cvta.to.shared.u64 t, %1; cvt.u32.u64 %0, t; }" : "=r"(a) : "l"(p));
    return a;
}
__device__ __forceinline__ void ldsm_x4(uint32_t* d, uint32_t addr) {
    asm volatile("ldmatrix.sync.aligned.m8n8.x4.shared.b16 {%0,%1,%2,%3}, [%4];"
        : "=r"(d[0]), "=r"(d[1]), "=r"(d[2]), "=r"(d[3]) : "r"(addr));
}
__device__ __forceinline__ void ldsm_x4t(uint32_t* d, uint32_t addr) {
    asm volatile("ldmatrix.sync.aligned.m8n8.x4.trans.shared.b16 {%0,%1,%2,%3}, [%4];"
        : "=r"(d[0]), "=r"(d[1]), "=r"(d[2]), "=r"(d[3]) : "r"(addr));
}
__device__ __forceinline__ void mma16816(float* c, const uint32_t* a, uint32_t b0, uint32_t b1) {
    asm volatile("mma.sync.aligned.m16n8k16.row.col.f32.f16.f16.f32 "
        "{%0,%1,%2,%3}, {%4,%5,%6,%7}, {%8,%9}, {%0,%1,%2,%3};"
        : "+f"(c[0]), "+f"(c[1]), "+f"(c[2]), "+f"(c[3])
        : "r"(a[0]), "r"(a[1]), "r"(a[2]), "r"(a[3]), "r"(b0), "r"(b1));
}

// ============================================================
// 0) adjacency -> bitmask
// ============================================================
__global__ __launch_bounds__(256) void mask_kernel(const int* __restrict__ adj)
{
    int gid = blockIdx.x * 256 + threadIdx.x;
    unsigned word = __ballot_sync(0xffffffffu, adj[gid] > 0);
    if ((threadIdx.x & 31) == 0) g_mask[gid >> 5] = word;
}

// ============================================================
// 1) h = x @ W : f32x2 64x128 tiles -> fp32 g_h + fp16 g_hh
// ============================================================
__global__ __launch_bounds__(256) void gemm_kernel(const float* __restrict__ A,
                                                   const float* __restrict__ Bm)
{
    __shared__ __align__(16) float Astd[32 * 130];
    __shared__ __align__(16) float Bs[32 * 128];

    int t  = threadIdx.x;
    int ty = t >> 4, tx = t & 15;
    int rowBase = blockIdx.y << 6;
    int colBase = blockIdx.x << 7;

    unsigned long long acc[4][4];
    #pragma unroll
    for (int r = 0; r < 4; ++r)
        #pragma unroll
        for (int q = 0; q < 4; ++q) acc[r][q] = 0ull;

    for (int k0 = 0; k0 < 256; k0 += 32) {
        #pragma unroll
        for (int l = 0; l < 8; ++l) {
            int idx = t + (l << 8);
            int ar = idx >> 5, ak = idx & 31;
            float v = A[(rowBase + ar) * 256 + k0 + ak];
            *(float2*)&Astd[ak * 130 + (ar << 1)] = make_float2(v, v);
        }
        #pragma unroll
        for (int l = 0; l < 4; ++l) {
            int idx = t + (l << 8);
            int bk = idx >> 5, bc4 = idx & 31;
            *(float4*)&Bs[bk * 128 + (bc4 << 2)] =
                *(const float4*)&Bm[(k0 + bk) * 256 + colBase + (bc4 << 2)];
        }
        __syncthreads();
        #pragma unroll 8
        for (int kk = 0; kk < 32; ++kk) {
            ulonglong2 B0 = *(const ulonglong2*)&Bs[kk * 128 + (tx << 3)];
            ulonglong2 B1 = *(const ulonglong2*)&Bs[kk * 128 + (tx << 3) + 4];
            #pragma unroll
            for (int r = 0; r < 4; ++r) {
                unsigned long long a2 =
                    *(const unsigned long long*)&Astd[kk * 130 + (((ty << 2) + r) << 1)];
                fma2(acc[r][0], a2, B0.x);
                fma2(acc[r][1], a2, B0.y);
                fma2(acc[r][2], a2, B1.x);
                fma2(acc[r][3], a2, B1.y);
            }
        }
        __syncthreads();
    }
    #pragma unroll
    for (int r = 0; r < 4; ++r) {
        float2 c0 = unpack2(acc[r][0]);
        float2 c1 = unpack2(acc[r][1]);
        float2 c2 = unpack2(acc[r][2]);
        float2 c3 = unpack2(acc[r][3]);
        int off = (rowBase + (ty << 2) + r) * 256 + colBase + (tx << 3);
        *(float4*)&g_h[off]     = make_float4(c0.x, c0.y, c1.x, c1.y);
        *(float4*)&g_h[off + 4] = make_float4(c2.x, c2.y, c3.x, c3.y);
        __half2 h0 = __floats2half2_rn(c0.x, c0.y);
        __half2 h1 = __floats2half2_rn(c1.x, c1.y);
        __half2 h2 = __floats2half2_rn(c2.x, c2.y);
        __half2 h3 = __floats2half2_rn(c3.x, c3.y);
        *(uint4*)((unsigned short*)g_hh + off) =
            make_uint4(*(uint32_t*)&h0, *(uint32_t*)&h1, *(uint32_t*)&h2, *(uint32_t*)&h3);
    }
}

// ============================================================
// 2) scores from fp32 h
// ============================================================
__global__ __launch_bounds__(256) void score_kernel(const float* __restrict__ a)
{
    int bn = blockIdx.x;
    int c  = threadIdx.x;
    float hv = g_h[bn * 256 + c];
    int hd = c >> 6, d = c & 63;
    float ps = hv * a[d * 4 + hd];
    float pd = hv * a[(64 + d) * 4 + hd];
    #pragma unroll
    for (int o = 16; o; o >>= 1) {
        ps += __shfl_xor_sync(0xffffffffu, ps, o);
        pd += __shfl_xor_sync(0xffffffffu, pd, o);
    }
    __shared__ float rs[8], rd[8];
    if ((c & 31) == 0) { rs[c >> 5] = ps; rd[c >> 5] = pd; }
    __syncthreads();
    if (c < 4) {
        g_ssrc[bn * 4 + c] = rs[2 * c] + rs[2 * c + 1];
        g_sdst[bn * 4 + c] = rd[2 * c] + rd[2 * c + 1];
    }
}

// ============================================================
// 3) g_mx[b,h] = max_n s_dst[b,n,h]
// ============================================================
__global__ __launch_bounds__(256) void max_kernel()
{
    int bh = blockIdx.x;
    int b = bh >> 2, h = bh & 3;
    int t = threadIdx.x;
    float m = -3.4e38f;
    for (int n = t; n < NN; n += 256)
        m = fmaxf(m, g_sdst[((b << 10) + n) * 4 + h]);
    #pragma unroll
    for (int o = 16; o; o >>= 1) m = fmaxf(m, __shfl_xor_sync(0xffffffffu, m, o));
    __shared__ float sm_[8];
    if ((t & 31) == 0) sm_[t >> 5] = m;
    __syncthreads();
    if (t == 0) {
        float mm = sm_[0];
        #pragma unroll
        for (int i = 1; i < 8; ++i) mm = fmaxf(mm, sm_[i]);
        g_mx[bh] = mm;
    }
}

// ============================================================
// 4) HMMA attention aggregation (mma.sync m16n8k16 fp16 -> f32).
//    CTA = (b, 128-row i-tile), 512 threads / 16 warps, grid 128.
//    Warp (ig = w&7, hg = w>>3): rows ig*16.., heads 2hg, 2hg+1.
// ============================================================
__global__ __launch_bounds__(512, 1)
void attn_mma_kernel(float* __restrict__ out)
{
    extern __shared__ __align__(16) char sb[];
    const uint32_t sbS = smem_u32(sb);
    const uint32_t sbH = sbS + H_OFF;

    __shared__ float4 sdst_s[NN];                  // 16 KB
    __shared__ float4 ssrc_s[128], Ms_s[128];
    __shared__ float4 den_part[4][128];            // 8 KB

    const int t = threadIdx.x;
    const int lane = t & 31, w = t >> 5;
    const int b  = blockIdx.x >> 3;
    const int i0 = (blockIdx.x & 7) << 7;

    for (int k = t; k < NN; k += 512)
        sdst_s[k] = ((const float4*)g_sdst)[(b << 10) + k];
    if (t < 128) {
        float4 ss = ((const float4*)g_ssrc)[(b << 10) + i0 + t];
        ssrc_s[t] = ss;
        float4 mx = ((const float4*)g_mx)[b];
        float4 M;
        M.x = ss.x + mx.x; M.x = fmaxf(M.x, NEG_SLOPE * M.x);
        M.y = ss.y + mx.y; M.y = fmaxf(M.y, NEG_SLOPE * M.y);
        M.z = ss.z + mx.z; M.z = fmaxf(M.z, NEG_SLOPE * M.z);
        M.w = ss.w + mx.w; M.w = fmaxf(M.w, NEG_SLOPE * M.w);
        Ms_s[t] = M;
    }
    __syncthreads();

    // weight-phase identity: row iw, 16-j chunk jc
    const int iw = t & 127;
    const int jc = t >> 7;
    const float4 ss4 = ssrc_s[iw], Ms4 = Ms_s[iw];
    const unsigned* mrow = &g_mask[(((b << 10) + i0 + iw) << 5)];
    const uint32_t sAddrW = sbS + iw * SROW + (jc << 5);   // byte addr of this 16-j chunk
    float den0 = 0.f, den1 = 0.f, den2 = 0.f, den3 = 0.f;

    // mma-phase identity
    const int ig = w & 7, hg = w >> 3;
    const int q = lane >> 3, r = lane & 7;
    const uint32_t aBase = sbS + ((ig << 4) + ((q & 1) << 3) + r) * SROW + ((q >> 1) << 4);
    const uint32_t bBase = sbH + (lane & 15) * HROW + ((lane >> 4) << 4);

    float acc[2][8][4];
    #pragma unroll
    for (int hl = 0; hl < 2; ++hl)
        #pragma unroll
        for (int n = 0; n < 8; ++n)
            #pragma unroll
            for (int c = 0; c < 4; ++c) acc[hl][n][c] = 0.f;

    const uint4* hh4 = (const uint4*)g_hh;
    const int hgbase = (b << 10) << 5;             // uint4 row base for batch b

    for (int jt = 0; jt < 16; ++jt) {
        const int j0 = jt << 6;
        __syncthreads();   // prior mma phase done before overwriting S/H

        // -- H tile: 64 rows x 512B
        {
            const int gb = hgbase + (j0 << 5);
            #pragma unroll
            for (int l = 0; l < 4; ++l) {
                int idx = t + (l << 9);
                uint4 v = hh4[gb + idx];
                *(uint4*)(sb + H_OFF + (idx >> 5) * HROW + ((idx & 31) << 4)) = v;
            }
        }

        // -- S tile: (iw, 16 j's), 4 heads; two 8-j groups -> uint4 store each
        {
            unsigned mw = mrow[(jt << 1) + (jc >> 1)] >> ((jc & 1) << 4);
            #pragma unroll
            for (int gHalf = 0; gHalf < 2; ++gHalf) {
                uint32_t pk[4][4];
                float wl[4];
                #pragma unroll
                for (int pp = 0; pp < 8; ++pp) {
                    int jl = (gHalf << 3) + pp;
                    float4 sd = sdst_s[j0 + (jc << 4) + jl];
                    float msk = ((mw >> jl) & 1u) ? 1.f : 0.f;
                    float e0 = ss4.x + sd.x; e0 = fmaxf(e0, NEG_SLOPE * e0);
                    float e1 = ss4.y + sd.y; e1 = fmaxf(e1, NEG_SLOPE * e1);
                    float e2 = ss4.z + sd.z; e2 = fmaxf(e2, NEG_SLOPE * e2);
                    float e3 = ss4.w + sd.w; e3 = fmaxf(e3, NEG_SLOPE * e3);
                    float w0 = msk * __expf(e0 - Ms4.x);
                    float w1 = msk * __expf(e1 - Ms4.y);
                    float w2 = msk * __expf(e2 - Ms4.z);
                    float w3 = msk * __expf(e3 - Ms4.w);
                    den0 += w0; den1 += w1; den2 += w2; den3 += w3;
                    if (pp & 1) {
                        __half2 p0 = __floats2half2_rn(wl[0], w0);
                        __half2 p1 = __floats2half2_rn(wl[1], w1);
                        __half2 p2 = __floats2half2_rn(wl[2], w2);
                        __half2 p3 = __floats2half2_rn(wl[3], w3);
                        pk[0][pp >> 1] = *(uint32_t*)&p0;
                        pk[1][pp >> 1] = *(uint32_t*)&p1;
                        pk[2][pp >> 1] = *(uint32_t*)&p2;
                        pk[3][pp >> 1] = *(uint32_t*)&p3;
                    } else { wl[0] = w0; wl[1] = w1; wl[2] = w2; wl[3] = w3; }
                }
                #pragma unroll
                for (int hh = 0; hh < 4; ++hh) {
                    uint4 v = make_uint4(pk[hh][0], pk[hh][1], pk[hh][2], pk[hh][3]);
                    asm volatile("st.shared.v4.b32 [%0], {%1,%2,%3,%4};"
                        :: "r"(sAddrW + hh * SSIZE + (gHalf << 4)),
                           "r"(v.x), "r"(v.y), "r"(v.z), "r"(v.w) : "memory");
                }
            }
        }
        __syncthreads();

        // -- MMA phase: 4 k-steps x (2 A ldsm.x4 + 4 B ldsm.x4.trans + 8 mma)
        #pragma unroll
        for (int ks = 0; ks < 4; ++ks) {
            uint32_t A[2][4];
            #pragma unroll
            for (int hl = 0; hl < 2; ++hl)
                ldsm_x4(A[hl], aBase + (((hg << 1) + hl) * SSIZE) + (ks << 5));
            #pragma unroll
            for (int hl = 0; hl < 2; ++hl) {
                #pragma unroll
                for (int p = 0; p < 4; ++p) {
                    uint32_t Bf[4];
                    ldsm_x4t(Bf, bBase + ks * (16 * HROW)
                                 + (((hg << 7) + (hl << 6) + (p << 4)) << 1));
                    mma16816(acc[hl][2 * p],     A[hl], Bf[0], Bf[1]);
                    mma16816(acc[hl][2 * p + 1], A[hl], Bf[2], Bf[3]);
                }
            }
        }
    }

    den_part[jc][iw] = make_float4(den0, den1, den2, den3);
    __syncthreads();
    if (t < 128) {
        float4 d0 = den_part[0][t], d1 = den_part[1][t], d2 = den_part[2][t], d3 = den_part[3][t];
        den_part[0][t] = make_float4(d0.x + d1.x + d2.x + d3.x,
                                     d0.y + d1.y + d2.y + d3.y,
                                     d0.z + d1.z + d2.z + d3.z,
                                     d0.w + d1.w + d2.w + d3.w);
    }
    __syncthreads();

    const float* denf = (const float*)&den_part[0][0];
    const int row_lo = (ig << 4) + (lane >> 2);
    #pragma unroll
    for (int hl = 0; hl < 2; ++hl) {
        int head = (hg << 1) + hl;
        float dv0 = 1.f / denf[row_lo * 4 + head];
        float dv1 = 1.f / denf[(row_lo + 8) * 4 + head];
        #pragma unroll
        for (int n = 0; n < 8; ++n) {
            int col = (head << 6) + (n << 3) + ((lane & 3) << 1);
            *(float2*)(out + ((b << 10) + i0 + row_lo) * 256 + col) =
                make_float2(acc[hl][n][0] * dv0, acc[hl][n][1] * dv0);
            *(float2*)(out + ((b << 10) + i0 + row_lo + 8) * 256 + col) =
                make_float2(acc[hl][n][2] * dv1, acc[hl][n][3] * dv1);
        }
    }
}

// ============================================================
extern "C" void kernel_launch(void* const* d_in, const int* in_sizes, int n_in,
                              void* d_out, int out_size)
{
    cudaFuncSetAttribute(attn_mma_kernel, cudaFuncAttributeMaxDynamicSharedMemorySize, DYN_BYTES);

    const float* x = nullptr; const int* adj = nullptr;
    const float* W = nullptr; const float* a = nullptr;
    for (int i = 0; i < n_in; ++i) {
        int s = in_sizes[i];
        if      (s == BB * NN * INF) x   = (const float*)d_in[i];
        else if (s == BB * NN * NN)  adj = (const int*)d_in[i];
        else if (s == INF * HH * DD) W   = (const float*)d_in[i];
        else if (s == 2 * DD * HH)   a   = (const float*)d_in[i];
    }

    mask_kernel<<<BB * NN * NN / 256, 256>>>(adj);
    gemm_kernel<<<dim3(2, 256), 256>>>(x, W);
    score_kernel<<<BB * NN, 256>>>(a);
    max_kernel<<<BB * HH, 256>>>();
    attn_mma_kernel<<<BB * (NN / 128), 512, DYN_BYTES>>>((float*)d_out);
}